// round 11
// baseline (speedup 1.0000x reference)
#include <cuda_runtime.h>
#include <cuda_bf16.h>
#include <math.h>
#include <stdint.h>

#define VOCAB  50000
#define BATCH  1024
#define SEQ    120
#define EMBED  50
#define HIDDEN 300
#define NCLASS 5
#define GATES  1200   // 4*HIDDEN, packed as col' = 4*hh + gate (i,j,f,o)

// LSTM persistent kernel geometry
#define MT 8
#define NT 15
#define NBLK (MT*NT)       // 120 blocks, 1 per SM
#define BM 128
#define BN 80              // 80 gate cols = 20 hidden units per tile
#define KPAD 320           // K=300 padded to 20 k16 steps
#define BSTRIDE 328        // B row stride (elems), conflict-free LDSM
#define ASTRIDE_E 88       // A chunk row stride (elems)
#define CHUNK_K 80         // 5 k16-steps per chunk, 4 chunks

// smem byte offsets
#define SMB_BHI 0
#define SMB_BLO 52480
#define SMB_AHI 104960
#define SMB_ALO 127488
#define SMEM_BYTES_L 150016

// proj kernel
#define PROJ_ROWS 128
#define HSTRIDE 308
#define PROJ_SMEM ((PROJ_ROWS*HSTRIDE + HIDDEN*NCLASS + PROJ_ROWS*NCLASS + 8)*4)

typedef unsigned long long u64;

// ---------------- scratch ----------------
__device__ float EW_buf[(size_t)VOCAB * GATES];
__device__ float Hall_buf[(size_t)SEQ * BATCH * HIDDEN];
__device__ float C_buf[BATCH * HIDDEN];
__device__ uint4 Bhi_g4[(NT * BN * BSTRIDE * 2) / 16];   // bf16 hi image
__device__ uint4 Blo_g4[(NT * BN * BSTRIDE * 2) / 16];   // bf16 lo image

__device__ unsigned bar_arrive[MT];
__device__ unsigned bar_gen[MT];

// ---------------- helpers ----------------
__device__ __forceinline__ unsigned ld_volatile_u32(unsigned* p) {
    unsigned v;
    asm volatile("ld.volatile.global.u32 %0, [%1];" : "=r"(v) : "l"(p));
    return v;
}
__device__ __forceinline__ float sigf(float x) { return 1.0f / (1.0f + expf(-x)); }

__device__ __forceinline__ u64 pack2(float lo, float hi) {
    u64 r; asm("mov.b64 %0, {%1, %2};" : "=l"(r) : "f"(lo), "f"(hi)); return r;
}
__device__ __forceinline__ void unpack2(u64 v, float& lo, float& hi) {
    asm("mov.b64 {%0, %1}, %2;" : "=f"(lo), "=f"(hi) : "l"(v));
}
__device__ __forceinline__ u64 ffma2(u64 a, u64 b, u64 c) {
    u64 d; asm("fma.rn.f32x2 %0, %1, %2, %3;" : "=l"(d) : "l"(a), "l"(b), "l"(c));
    return d;
}
__device__ __forceinline__ uint32_t smem_u32(const void* p) {
    uint32_t a;
    asm("{ .reg .u64 t; cvta.to.shared.u64 t, %1; cvt.u32.u64 %0, t; }"
        : "=r"(a) : "l"(p));
    return a;
}

#define LDSM_X4(r, addr)                                                        \
    asm volatile("ldmatrix.sync.aligned.m8n8.x4.shared.b16 {%0,%1,%2,%3}, [%4];" \
        : "=r"((r)[0]), "=r"((r)[1]), "=r"((r)[2]), "=r"((r)[3]) : "r"(addr))
#define LDSM_X2(r, addr)                                                        \
    asm volatile("ldmatrix.sync.aligned.m8n8.x2.shared.b16 {%0,%1}, [%2];"      \
        : "=r"((r)[0]), "=r"((r)[1]) : "r"(addr))

__device__ __forceinline__ void mma_bf16(float* c, const uint32_t* a, const uint32_t* b) {
    asm volatile(
        "mma.sync.aligned.m16n8k16.row.col.f32.bf16.bf16.f32 "
        "{%0,%1,%2,%3}, {%4,%5,%6,%7}, {%8,%9}, {%0,%1,%2,%3};"
        : "+f"(c[0]), "+f"(c[1]), "+f"(c[2]), "+f"(c[3])
        : "r"(a[0]), "r"(a[1]), "r"(a[2]), "r"(a[3]), "r"(b[0]), "r"(b[1]));
}

// ---------------------------------------------------------------------------
// EW[v][col'] = b_lstm[orig(col')] + sum_e emb[v][e] * W[e][orig(col')]
// (proven from R7)
// ---------------------------------------------------------------------------
__global__ __launch_bounds__(256) void ew_kernel(const float* __restrict__ emb,
                                                 const float* __restrict__ W,
                                                 const float* __restrict__ bl) {
    __shared__ float Ast[EMBED * 68];
    __shared__ float Bs[EMBED * 68];

    int tid = threadIdx.x;
    int tx = tid & 15, ty = tid >> 4;
    int rowBase = blockIdx.y * 64;
    int colBase = blockIdx.x * 64;

    for (int idx = tid; idx < 64 * EMBED; idx += 256) {
        int r = idx / EMBED, k = idx % EMBED;
        int v = rowBase + r;
        Ast[k * 68 + r] = (v < VOCAB) ? emb[(size_t)v * EMBED + k] : 0.f;
    }
    for (int idx = tid; idx < EMBED * 64; idx += 256) {
        int k = idx >> 6, c = idx & 63;
        int col = colBase + c;
        float val = 0.f;
        if (col < GATES) {
            int g = col & 3, hh = col >> 2;
            val = W[(size_t)k * GATES + g * HIDDEN + hh];
        }
        Bs[k * 68 + c] = val;
    }
    __syncthreads();

    u64 acc[2][4];
    #pragma unroll
    for (int p = 0; p < 2; p++)
        #pragma unroll
        for (int j = 0; j < 4; j++) acc[p][j] = 0ull;

    #pragma unroll 5
    for (int k = 0; k < EMBED; k++) {
        ulonglong2 A0 = *(const ulonglong2*)&Ast[k * 68 + ty * 4];
        float4 b4 = *(const float4*)&Bs[k * 68 + tx * 4];
        u64 bd0 = pack2(b4.x, b4.x), bd1 = pack2(b4.y, b4.y);
        u64 bd2 = pack2(b4.z, b4.z), bd3 = pack2(b4.w, b4.w);
        acc[0][0] = ffma2(A0.x, bd0, acc[0][0]);
        acc[0][1] = ffma2(A0.x, bd1, acc[0][1]);
        acc[0][2] = ffma2(A0.x, bd2, acc[0][2]);
        acc[0][3] = ffma2(A0.x, bd3, acc[0][3]);
        acc[1][0] = ffma2(A0.y, bd0, acc[1][0]);
        acc[1][1] = ffma2(A0.y, bd1, acc[1][1]);
        acc[1][2] = ffma2(A0.y, bd2, acc[1][2]);
        acc[1][3] = ffma2(A0.y, bd3, acc[1][3]);
    }

    int col0 = colBase + tx * 4;
    if (col0 < GATES) {
        int hh = col0 >> 2;
        float bias[4];
        #pragma unroll
        for (int j = 0; j < 4; j++) bias[j] = bl[j * HIDDEN + hh];
        #pragma unroll
        for (int p = 0; p < 2; p++) {
            float lo[4], hi[4];
            #pragma unroll
            for (int j = 0; j < 4; j++) unpack2(acc[p][j], lo[j], hi[j]);
            int v0 = rowBase + ty * 4 + p * 2;
            if (v0 < VOCAB) {
                float4 o = make_float4(lo[0] + bias[0], lo[1] + bias[1],
                                       lo[2] + bias[2], lo[3] + bias[3]);
                *(float4*)&EW_buf[(size_t)v0 * GATES + col0] = o;
            }
            if (v0 + 1 < VOCAB) {
                float4 o = make_float4(hi[0] + bias[0], hi[1] + bias[1],
                                       hi[2] + bias[2], hi[3] + bias[3]);
                *(float4*)&EW_buf[(size_t)(v0 + 1) * GATES + col0] = o;
            }
        }
    }
}

// ---------------------------------------------------------------------------
// Pack Whp into bf16 hi/lo B images: B[tile][n][k] = Whp[k][tile*80+n],
// [n][k] layout, k contiguous, row stride 328, zeros for k>=300.
// ---------------------------------------------------------------------------
__global__ void pack_b(const float* __restrict__ W) {
    int idx = blockIdx.x * 256 + threadIdx.x;
    if (idx >= NT * BN * BSTRIDE) return;
    int tile = idx / (BN * BSTRIDE);
    int rem  = idx % (BN * BSTRIDE);
    int n = rem / BSTRIDE;
    int k = rem % BSTRIDE;
    int col = tile * BN + n;
    int orig = (col & 3) * HIDDEN + (col >> 2);
    float w = (k < HIDDEN) ? W[(size_t)(EMBED + k) * GATES + orig] : 0.f;
    __nv_bfloat16 hi = __float2bfloat16_rn(w);
    __nv_bfloat16 lo = __float2bfloat16_rn(w - __bfloat162float(hi));
    ((__nv_bfloat16*)Bhi_g4)[idx] = hi;
    ((__nv_bfloat16*)Blo_g4)[idx] = lo;
}

// ---------------------------------------------------------------------------
// Persistent LSTM scan, warp-level bf16 HMMA 3-pass (hi*hi + hi*lo + lo*hi).
// 120 blocks = 8 M-tiles(128 rows) x 15 N-tiles(80 gate cols). 8 warps =
// 4 m-groups(32 rows) x 2 n-groups(40 cols); per warp 2x5 m16n8 f32 frags.
// B hi/lo resident in smem; A staged per 80-K chunk with bf16 split.
// ---------------------------------------------------------------------------
__global__ __launch_bounds__(256, 1) void lstm_persist(const int* __restrict__ ids) {
    extern __shared__ char smem[];
    const uint32_t smem_base = smem_u32(smem);
    const int tid = threadIdx.x;
    const int wid = tid >> 5;
    const int lane = tid & 31;
    const int wm = wid & 3;        // m-group: rows wm*32..wm*32+31
    const int wn = wid >> 2;       // n-group: cols wn*40..wn*40+39
    const int mt = blockIdx.x % MT;
    const int nt = blockIdx.x / MT;
    const int rowBase = mt * BM;
    const int colBase = nt * BN;

    // copy resident B images
    {
        const int nv = (BN * BSTRIDE * 2) / 16;   // 3280 uint4 per image
        const uint4* gH = &Bhi_g4[(size_t)nt * nv];
        const uint4* gL = &Blo_g4[(size_t)nt * nv];
        uint4* sH = (uint4*)(smem + SMB_BHI);
        uint4* sL = (uint4*)(smem + SMB_BLO);
        for (int i = tid; i < nv; i += 256) { sH[i] = gH[i]; sL[i] = gL[i]; }
    }
    __syncthreads();

    // ldmatrix base addresses (lane-dependent parts precomputed)
    const uint32_t aRow = wm * 32 + (lane & 15);         // + mi*16
    const uint32_t aColOff = (lane >> 4) * 8;            // + kk (chunk-local)
    const uint32_t bRow = wn * 40 + (lane & 7);          // + ni*8
    const uint32_t bColOff = ((lane >> 3) & 1) * 8;      // + k global

    for (int t = 0; t < SEQ; t++) {
        float acc[2][5][4];
        #pragma unroll
        for (int mi = 0; mi < 2; mi++)
            #pragma unroll
            for (int ni = 0; ni < 5; ni++)
                #pragma unroll
                for (int q = 0; q < 4; q++) acc[mi][ni][q] = 0.f;

        if (t > 0) {
            const float* hprev =
                &Hall_buf[(size_t)(t - 1) * BATCH * HIDDEN + (size_t)rowBase * HIDDEN];
            const int sr = tid >> 1, shalf = tid & 1;   // staging: 2 threads/row

            for (int cc = 0; cc < 4; cc++) {
                const int k0g = cc * CHUNK_K;
                __syncthreads();   // previous chunk's ldmatrix reads done
                // stage A chunk: 128 rows x 80 k, bf16 hi/lo split
                #pragma unroll
                for (int i = 0; i < 10; i++) {
                    int k = shalf * 40 + i * 4;
                    float4 v = make_float4(0.f, 0.f, 0.f, 0.f);
                    if (k0g + k < HIDDEN)
                        v = *(const float4*)&hprev[(size_t)sr * HIDDEN + k0g + k];
                    __nv_bfloat16 h0 = __float2bfloat16_rn(v.x);
                    __nv_bfloat16 h1 = __float2bfloat16_rn(v.y);
                    __nv_bfloat16 h2 = __float2bfloat16_rn(v.z);
                    __nv_bfloat16 h3 = __float2bfloat16_rn(v.w);
                    __nv_bfloat16 l0 = __float2bfloat16_rn(v.x - __bfloat162float(h0));
                    __nv_bfloat16 l1 = __float2bfloat16_rn(v.y - __bfloat162float(h1));
                    __nv_bfloat16 l2 = __float2bfloat16_rn(v.z - __bfloat162float(h2));
                    __nv_bfloat16 l3 = __float2bfloat16_rn(v.w - __bfloat162float(h3));
                    uint2 hv, lv;
                    hv.x = ((uint32_t)__bfloat16_as_ushort(h1) << 16) | __bfloat16_as_ushort(h0);
                    hv.y = ((uint32_t)__bfloat16_as_ushort(h3) << 16) | __bfloat16_as_ushort(h2);
                    lv.x = ((uint32_t)__bfloat16_as_ushort(l1) << 16) | __bfloat16_as_ushort(l0);
                    lv.y = ((uint32_t)__bfloat16_as_ushort(l3) << 16) | __bfloat16_as_ushort(l2);
                    uint32_t off = (uint32_t)(sr * ASTRIDE_E + k) * 2;
                    *(uint2*)(smem + SMB_AHI + off) = hv;
                    *(uint2*)(smem + SMB_ALO + off) = lv;
                }
                __syncthreads();

                #pragma unroll
                for (int ks = 0; ks < 5; ks++) {
                    const int kk = ks * 16;
                    uint32_t ah[2][4], al[2][4];
                    #pragma unroll
                    for (int mi = 0; mi < 2; mi++) {
                        uint32_t off =
                            ((aRow + mi * 16) * ASTRIDE_E + kk + aColOff) * 2;
                        LDSM_X4(ah[mi], smem_base + SMB_AHI + off);
                        LDSM_X4(al[mi], smem_base + SMB_ALO + off);
                    }
                    uint32_t bh[5][2], bl[5][2];
                    #pragma unroll
                    for (int ni = 0; ni < 5; ni++) {
                        uint32_t off =
                            ((bRow + ni * 8) * BSTRIDE + k0g + kk + bColOff) * 2;
                        LDSM_X2(bh[ni], smem_base + SMB_BHI + off);
                        LDSM_X2(bl[ni], smem_base + SMB_BLO + off);
                    }
                    #pragma unroll
                    for (int mi = 0; mi < 2; mi++)
                        #pragma unroll
                        for (int ni = 0; ni < 5; ni++) {
                            mma_bf16(acc[mi][ni], ah[mi], bh[ni]);
                            mma_bf16(acc[mi][ni], ah[mi], bl[ni]);
                            mma_bf16(acc[mi][ni], al[mi], bh[ni]);
                        }
                }
            }
        }

        // ---- fused gate epilogue (shfl reassembles 4-col gate groups) ----
        {
            const int rloc = (lane >> 2) + ((lane & 1) << 3);
            const int grp = (lane & 3) >> 1;
            #pragma unroll
            for (int mi = 0; mi < 2; mi++) {
                const int b = rowBase + wm * 32 + mi * 16 + rloc;
                const int id = __ldg(&ids[(size_t)b * SEQ + t]);
                const size_t ewRow = (size_t)id * GATES;
                float* hallRow = &Hall_buf[((size_t)t * BATCH + b) * HIDDEN];
                #pragma unroll
                for (int ni = 0; ni < 5; ni++) {
                    const float* c = acc[mi][ni];
                    u64 send = (lane & 1) ? pack2(c[0], c[1]) : pack2(c[2], c[3]);
                    u64 recv = __shfl_xor_sync(0xffffffffu, send, 1);
                    float r0, r1;
                    unpack2(recv, r0, r1);
                    float z0, z1, z2, z3;
                    if (!(lane & 1)) { z0 = c[0]; z1 = c[1]; z2 = r0; z3 = r1; }
                    else             { z0 = r0; z1 = r1; z2 = c[2]; z3 = c[3]; }
                    const int col4 = colBase + wn * 40 + ni * 8 + grp * 4;
                    const int hh = col4 >> 2;
                    float4 ew = *(const float4*)&EW_buf[ewRow + col4];
                    float zi = z0 + ew.x, zj = z1 + ew.y;
                    float zf = z2 + ew.z, zo = z3 + ew.w;
                    float cprev = (t == 0) ? 0.f : C_buf[b * HIDDEN + hh];
                    float cn = cprev * sigf(zf + 1.0f) + sigf(zi) * tanhf(zj);
                    float hn = tanhf(cn) * sigf(zo);
                    C_buf[b * HIDDEN + hh] = cn;
                    hallRow[hh] = hn;
                }
            }
        }

        // ---- per-M-tile barrier (15 blocks share mt) ----
        if (t < SEQ - 1) {
            __threadfence();
            __syncthreads();
            if (tid == 0) {
                unsigned gen = ld_volatile_u32(&bar_gen[mt]);
                if (atomicAdd(&bar_arrive[mt], 1u) == NT - 1) {
                    atomicExch(&bar_arrive[mt], 0u);
                    __threadfence();
                    atomicExch(&bar_gen[mt], gen + 1);
                } else {
                    int spins = 0;
                    while (ld_volatile_u32(&bar_gen[mt]) == gen) {
                        if (++spins > 16) __nanosleep(128);
                    }
                }
                __threadfence();
            }
            __syncthreads();
        }
    }
}

// ---------------------------------------------------------------------------
// out[row][c] = Hall[row] @ U + b2. (proven from R9 design)
// ---------------------------------------------------------------------------
__global__ __launch_bounds__(256) void proj_kernel(const float* __restrict__ U,
                                                   const float* __restrict__ b2,
                                                   float* __restrict__ out) {
    extern __shared__ float psm[];
    float* Hs   = psm;                              // [128][308]
    float* Ut   = psm + PROJ_ROWS * HSTRIDE;        // [5][300]
    float* outS = Ut + HIDDEN * NCLASS;             // [128*5]
    float* b2s  = outS + PROJ_ROWS * NCLASS;

    const int tid = threadIdx.x;
    size_t rowBase = (size_t)blockIdx.x * PROJ_ROWS;
    const float* src = &Hall_buf[rowBase * HIDDEN];

    for (int i = tid; i < PROJ_ROWS * HIDDEN / 4; i += 256) {
        float4 v = *(const float4*)&src[i * 4];
        int r = (i * 4) / HIDDEN, hh = (i * 4) % HIDDEN;
        *(float4*)&Hs[r * HSTRIDE + hh] = v;
    }
    for (int i = tid; i < HIDDEN * NCLASS; i += 256) {
        int c = i / HIDDEN, hh = i % HIDDEN;
        Ut[i] = U[hh * NCLASS + c];
    }
    if (tid < NCLASS) b2s[tid] = b2[tid];
    __syncthreads();

    const int r = tid >> 1, half = tid & 1;
    const float* hrow = &Hs[r * HSTRIDE + half * 150];

    u64 acc[NCLASS];
    #pragma unroll
    for (int c = 0; c < NCLASS; c++) acc[c] = 0ull;
    #pragma unroll 5
    for (int i = 0; i < 75; i++) {
        u64 h2 = *(const u64*)&hrow[i * 2];
        #pragma unroll
        for (int c = 0; c < NCLASS; c++)
            acc[c] = ffma2(h2, *(const u64*)&Ut[c * HIDDEN + half * 150 + i * 2], acc[c]);
    }
    #pragma unroll
    for (int c = 0; c < NCLASS; c++) {
        float lo, hi;
        unpack2(acc[c], lo, hi);
        float s = lo + hi;
        s += __shfl_xor_sync(0xffffffffu, s, 1);
        if (half == 0) outS[r * NCLASS + c] = s + b2s[c];
    }
    __syncthreads();
    for (int i = tid; i < PROJ_ROWS * NCLASS; i += 256)
        out[rowBase * NCLASS + i] = outS[i];
}

// ---------------------------------------------------------------------------
extern "C" void kernel_launch(void* const* d_in, const int* in_sizes, int n_in,
                              void* d_out, int out_size) {
    const int*   ids = (const int*)d_in[0];     // (1024,120,1) int32
    const float* emb = (const float*)d_in[1];   // (50000,50)
    const float* W   = (const float*)d_in[2];   // (350,1200)
    const float* bl  = (const float*)d_in[3];   // (1200)
    const float* U   = (const float*)d_in[4];   // (300,5)
    const float* b2  = (const float*)d_in[5];   // (5)
    float* out = (float*)d_out;                 // (120,1024,5)

    cudaFuncSetAttribute(lstm_persist,
                         cudaFuncAttributeMaxDynamicSharedMemorySize, SMEM_BYTES_L);
    cudaFuncSetAttribute(proj_kernel,
                         cudaFuncAttributeMaxDynamicSharedMemorySize, PROJ_SMEM);

    dim3 ewgrid((GATES + 63) / 64, (VOCAB + 63) / 64);
    ew_kernel<<<ewgrid, 256>>>(emb, W, bl);
    pack_b<<<(NT * BN * BSTRIDE + 255) / 256, 256>>>(W);

    lstm_persist<<<NBLK, 256, SMEM_BYTES_L>>>(ids);

    proj_kernel<<<(SEQ * BATCH) / PROJ_ROWS, 256, PROJ_SMEM>>>(U, b2, out);
}